// round 1
// baseline (speedup 1.0000x reference)
#include <cuda_runtime.h>
#include <cuda_bf16.h>

// Problem: MultinomialCELoss
//   x: [N=8, Q=441, H=128, W=128] float32 (softmax probs)
//   y: [N=8, 2,    H=128, W=128] float32 (ab color values in [-110,110))
//   out[w] = -sum_{n,h} log( x[n, idx(n,h,w), h, w] )
//   idx = clip(floor((y0+110)/10),0,20)*21 + clip(floor((y1+110)/10),0,20)

#define N_  8
#define Q_  441
#define H_  128
#define W_  128
#define NBINS 21

__global__ void zero_out_kernel(float* out) {
    out[threadIdx.x] = 0.0f;
}

__device__ __forceinline__ int ab_bin(float v) {
    // Match JAX float32 semantics: floor((v - (-110)) / 10), clipped to [0,20].
    // __fdiv_rn forces IEEE round-to-nearest division even under fast-math.
    float q = floorf(__fdiv_rn(v + 110.0f, 10.0f));
    int qi = (int)q;
    qi = qi < 0 ? 0 : qi;
    qi = qi > (NBINS - 1) ? (NBINS - 1) : qi;
    return qi;
}

__global__ __launch_bounds__(W_) void mce_loss_kernel(
    const float* __restrict__ x,
    const float* __restrict__ y,
    float* __restrict__ out)
{
    const int w = threadIdx.x;   // 0..127
    const int h = blockIdx.x;    // 0..127
    const int hw = h * W_ + w;

    // Stage the y loads and index computation for all n first so the 8
    // scattered x gathers issue back-to-back (MLP = 8 per thread).
    int idx[N_];
    #pragma unroll
    for (int n = 0; n < N_; n++) {
        float ya = y[((size_t)n * 2 + 0) * (H_ * W_) + hw];
        float yb = y[((size_t)n * 2 + 1) * (H_ * W_) + hw];
        idx[n] = ab_bin(ya) * NBINS + ab_bin(yb);
    }

    float acc = 0.0f;
    float v[N_];
    #pragma unroll
    for (int n = 0; n < N_; n++) {
        v[n] = x[((size_t)n * Q_ + idx[n]) * (H_ * W_) + hw];
    }
    #pragma unroll
    for (int n = 0; n < N_; n++) {
        acc += logf(v[n]);
    }

    // One atomic per thread: 128 blocks * 128 threads = 16384 atomics,
    // 128 per output address — negligible L2-atomic serialization.
    atomicAdd(&out[w], -acc);
}

extern "C" void kernel_launch(void* const* d_in, const int* in_sizes, int n_in,
                              void* d_out, int out_size) {
    const float* x = (const float*)d_in[0];
    const float* y = (const float*)d_in[1];
    float* out = (float*)d_out;

    zero_out_kernel<<<1, W_>>>(out);
    mce_loss_kernel<<<H_, W_>>>(x, y, out);
}